// round 6
// baseline (speedup 1.0000x reference)
#include <cuda_runtime.h>
#include <cstdint>

// Problem constants
#define NBUCKETS 16
#define EMBD     1024
#define VOCAB    32000
#define SEQLEN   2048
#define RANK     8
#define BATCH    2
#define NTOK     (BATCH * SEQLEN)          // 4096 tokens
#define BUCKET_SHIFT 7                      // SEQLEN / NBUCKETS = 128 = 1<<7

// Scratch for the low-rank projection (alpha folded in): [NTOK][RANK]
__device__ float g_low[NTOK * RANK];

// ---------------------------------------------------------------------------
// Kernel 1 (v3 + PDL trigger): low = alpha * hidden @ A[bucket]
// 128 CTAs x 32 tokens, A bucket transposed in shared, 4 tokens/warp,
// split-butterfly reduce, coalesced 128B result line per warp.
// Ends with griddepcontrol.launch_dependents so the vocab kernel can start.
// ---------------------------------------------------------------------------
#define K1_TOKS 32
#define K1_TPB  256
#define TPW     4            // tokens per warp

__global__ __launch_bounds__(K1_TPB)
void lowproj_kernel(const float* __restrict__ hidden,
                    const float* __restrict__ A,
                    const float* __restrict__ alpha_p)
{
    __shared__ float sAT[RANK][EMBD];   // 32 KB, transposed A bucket

    const int tok0   = blockIdx.x * K1_TOKS;
    const int bucket = (tok0 & (SEQLEN - 1)) >> BUCKET_SHIFT;
    const float* __restrict__ Ab = A + (size_t)bucket * EMBD * RANK;

    // Cooperative load + transpose: 2048 float4, 8 per thread.
    for (int i = threadIdx.x; i < EMBD * RANK / 4; i += K1_TPB) {
        float4 v = reinterpret_cast<const float4*>(Ab)[i];
        const int e = i >> 1;
        const int q = (i & 1) * 4;
        sAT[q + 0][e] = v.x;
        sAT[q + 1][e] = v.y;
        sAT[q + 2][e] = v.z;
        sAT[q + 3][e] = v.w;
    }
    __syncthreads();

    const float alpha = alpha_p[0];
    const int wid  = threadIdx.x >> 5;
    const int lane = threadIdx.x & 31;
    const int wtok = tok0 + wid * TPW;           // first of this warp's 4 tokens
    const float* __restrict__ h0 = hidden + (size_t)wtok * EMBD;

    // acc value index i = g*8 + r  (g = token-in-warp, r = rank)
    float v[TPW * RANK];
#pragma unroll
    for (int i = 0; i < TPW * RANK; i++) v[i] = 0.0f;

    // lane covers e = lane*4 + k*128, k = 0..7
#pragma unroll
    for (int k = 0; k < EMBD / 128; k++) {
        const int e = lane * 4 + k * 128;
        float4 hv[TPW];
#pragma unroll
        for (int g = 0; g < TPW; g++)
            hv[g] = __ldcs(reinterpret_cast<const float4*>(h0 + (size_t)g * EMBD + e));
#pragma unroll
        for (int r = 0; r < RANK; r++) {
            const float4 av = *reinterpret_cast<const float4*>(&sAT[r][e]);
#pragma unroll
            for (int g = 0; g < TPW; g++) {
                v[g * RANK + r] = fmaf(hv[g].x, av.x,
                                  fmaf(hv[g].y, av.y,
                                  fmaf(hv[g].z, av.z,
                                  fmaf(hv[g].w, av.w, v[g * RANK + r]))));
            }
        }
    }

    // Split-butterfly reduce: 32 values across 32 lanes -> lane i holds the
    // lane-sum of value i. 31 shuffles total.
#pragma unroll
    for (int m = 16; m >= 1; m >>= 1) {
        const bool hi = (lane & m) != 0;
        const int h = m;
#pragma unroll
        for (int j = 0; j < 16; j++) {
            if (j < h) {
                float mine   = hi ? v[h + j] : v[j];
                float theirs = hi ? v[j]     : v[h + j];
                float other  = __shfl_xor_sync(0xFFFFFFFFu, theirs, m);
                v[j] = mine + other;
            }
        }
    }

    // lane l holds the sum for token g = l>>3, rank r = l&7.
    g_low[(size_t)wtok * RANK + lane] = v[0] * alpha;

    // Release the dependent (vocab) kernel. PTX griddepcontrol guarantees the
    // stores above are visible to reads after griddepcontrol.wait.
    cudaTriggerProgrammaticLaunchCompletion();
}

// ---------------------------------------------------------------------------
// Kernel 2 (+ PDL wait): out[bt][v] = sum_r low[bt][r] * B[r][v]
// B-panel register loads are independent of g_low, so they execute BEFORE the
// grid-dependency wait and overlap with lowproj's tail.
// ---------------------------------------------------------------------------
#define T_TILE 64
#define K2_THREADS 256
#define V4 (VOCAB / 4)        // 8000 float4 per row

__global__ __launch_bounds__(K2_THREADS, 4)
void vocabproj_kernel(const float* __restrict__ B,
                      float* __restrict__ out)
{
    const int v4  = blockIdx.x * K2_THREADS + threadIdx.x;  // float4 column index
    const bool valid = (v4 < V4);
    const int v = v4 * 4;

    // Independent work first: load B panel (8 rows x 4 cols) into registers.
    float4 b[RANK];
#pragma unroll
    for (int r = 0; r < RANK; r++) {
        if (valid)
            b[r] = *reinterpret_cast<const float4*>(B + (size_t)r * VOCAB + v);
        else
            b[r] = make_float4(0.f, 0.f, 0.f, 0.f);
    }

    // Wait for lowproj's stores to be visible.
    cudaGridDependencySynchronize();

    // Cooperative load of this block's token-tile of low into shared
    __shared__ float slow[T_TILE * RANK];    // 2 KB
    const int tok0 = blockIdx.y * T_TILE;
    for (int i = threadIdx.x; i < T_TILE * RANK / 4; i += K2_THREADS) {
        reinterpret_cast<float4*>(slow)[i] =
            reinterpret_cast<const float4*>(g_low + (size_t)tok0 * RANK)[i];
    }
    __syncthreads();

    if (!valid) return;

    float* __restrict__ op = out + (size_t)tok0 * VOCAB + v;

#pragma unroll 4
    for (int tt = 0; tt < T_TILE; tt++) {
        const float* l = slow + tt * RANK;   // broadcast shared reads
        float4 o;
        o.x = l[0] * b[0].x; o.y = l[0] * b[0].y; o.z = l[0] * b[0].z; o.w = l[0] * b[0].w;
#pragma unroll
        for (int r = 1; r < RANK; r++) {
            o.x = fmaf(l[r], b[r].x, o.x);
            o.y = fmaf(l[r], b[r].y, o.y);
            o.z = fmaf(l[r], b[r].z, o.z);
            o.w = fmaf(l[r], b[r].w, o.w);
        }
        __stcs(reinterpret_cast<float4*>(op), o);   // streaming store
        op += VOCAB;
    }
}

// ---------------------------------------------------------------------------
// Launch: lowproj normally, vocabproj with programmatic stream serialization
// so it launches while lowproj is still running and self-synchronizes via
// griddepcontrol.
// ---------------------------------------------------------------------------
extern "C" void kernel_launch(void* const* d_in, const int* in_sizes, int n_in,
                              void* d_out, int out_size)
{
    const float* hidden = (const float*)d_in[0];   // [2,2048,1024]
    const float* A      = (const float*)d_in[1];   // [16,1024,8]
    const float* B      = (const float*)d_in[2];   // [8,32000]
    const float* alpha  = (const float*)d_in[3];   // scalar
    float* out          = (float*)d_out;           // [2,2048,32000]

    lowproj_kernel<<<NTOK / K1_TOKS, K1_TPB>>>(hidden, A, alpha);

    dim3 grid2((V4 + K2_THREADS - 1) / K2_THREADS,   // 32
               NTOK / T_TILE);                       // 64

    cudaLaunchConfig_t cfg = {};
    cfg.gridDim  = grid2;
    cfg.blockDim = dim3(K2_THREADS, 1, 1);
    cfg.dynamicSmemBytes = 0;
    cfg.stream = 0;
    cudaLaunchAttribute attr[1];
    attr[0].id = cudaLaunchAttributeProgrammaticStreamSerialization;
    attr[0].val.programmaticStreamSerializationAllowed = 1;
    cfg.attrs = attr;
    cfg.numAttrs = 1;
    cudaLaunchKernelEx(&cfg, vocabproj_kernel, B, out);
}

// round 9
// speedup vs baseline: 1.0018x; 1.0018x over previous
#include <cuda_runtime.h>
#include <cstdint>

// Problem constants
#define NBUCKETS 16
#define EMBD     1024
#define VOCAB    32000
#define SEQLEN   2048
#define RANK     8
#define BATCH    2
#define NTOK     (BATCH * SEQLEN)          // 4096 tokens
#define BUCKET_SHIFT 7                      // SEQLEN / NBUCKETS = 128 = 1<<7

#define TILE_TOKS 32                        // tokens per tile (32 | 128: single bucket)
#define NTILES    (NTOK / TILE_TOKS)        // 128 producer CTAs / tiles
#define NCHUNKS   32                        // vocab chunks of 256 float4 each
#define TPB       256
#define TPW       4                         // tokens per warp (producer)
#define V4        (VOCAB / 4)               // 8000

// Scratch + handoff state (zero-initialized device globals; no allocation)
__device__ float    g_low[NTOK * RANK];
__device__ unsigned g_flag[NTILES];
__device__ unsigned g_cnt[NTILES];

// ---------------------------------------------------------------------------
// Fused kernel.
//   bid <  NTILES           : producer — low[tile] = alpha * hidden @ A[bucket]
//   bid >= NTILES           : consumer — out[tile tokens][chunk] = low @ B
// Producers publish per-tile flags (release); consumers spin (acquire) only on
// their own tile, so the vocab store stream starts ~3us after launch instead
// of after a global barrier. Last consumer of each tile resets flag/counter
// so graph replays are deterministic.
// ---------------------------------------------------------------------------
__global__ __launch_bounds__(TPB, 4)
void fused_kernel(const float* __restrict__ hidden,
                  const float* __restrict__ A,
                  const float* __restrict__ B,
                  const float* __restrict__ alpha_p,
                  float* __restrict__ out)
{
    const int bid = blockIdx.x;
    const int tid = threadIdx.x;

    if (bid < NTILES) {
        // ================= PRODUCER =================
        __shared__ float sAT[RANK][EMBD];   // 32 KB transposed A bucket

        const int tok0   = bid * TILE_TOKS;
        const int bucket = (tok0 & (SEQLEN - 1)) >> BUCKET_SHIFT;
        const float* __restrict__ Ab = A + (size_t)bucket * EMBD * RANK;

        // Cooperative load + transpose: 2048 float4, 8 per thread.
        for (int i = tid; i < EMBD * RANK / 4; i += TPB) {
            float4 v = reinterpret_cast<const float4*>(Ab)[i];
            const int e = i >> 1;
            const int q = (i & 1) * 4;
            sAT[q + 0][e] = v.x;
            sAT[q + 1][e] = v.y;
            sAT[q + 2][e] = v.z;
            sAT[q + 3][e] = v.w;
        }
        __syncthreads();

        const float alpha = alpha_p[0];
        const int wid  = tid >> 5;
        const int lane = tid & 31;
        const int wtok = tok0 + wid * TPW;
        const float* __restrict__ h0 = hidden + (size_t)wtok * EMBD;

        float v[TPW * RANK];
#pragma unroll
        for (int i = 0; i < TPW * RANK; i++) v[i] = 0.0f;

#pragma unroll
        for (int k = 0; k < EMBD / 128; k++) {
            const int e = lane * 4 + k * 128;
            float4 hv[TPW];
#pragma unroll
            for (int g = 0; g < TPW; g++)
                hv[g] = __ldcs(reinterpret_cast<const float4*>(h0 + (size_t)g * EMBD + e));
#pragma unroll
            for (int r = 0; r < RANK; r++) {
                const float4 av = *reinterpret_cast<const float4*>(&sAT[r][e]);
#pragma unroll
                for (int g = 0; g < TPW; g++) {
                    v[g * RANK + r] = fmaf(hv[g].x, av.x,
                                      fmaf(hv[g].y, av.y,
                                      fmaf(hv[g].z, av.z,
                                      fmaf(hv[g].w, av.w, v[g * RANK + r]))));
                }
            }
        }

        // Split-butterfly reduce: 32 accumulators across 32 lanes, 31 shuffles.
#pragma unroll
        for (int m = 16; m >= 1; m >>= 1) {
            const bool hi = (lane & m) != 0;
            const int h = m;
#pragma unroll
            for (int j = 0; j < 16; j++) {
                if (j < h) {
                    float mine   = hi ? v[h + j] : v[j];
                    float theirs = hi ? v[j]     : v[h + j];
                    float other  = __shfl_xor_sync(0xFFFFFFFFu, theirs, m);
                    v[j] = mine + other;
                }
            }
        }

        // lane l = token g=l>>3, rank r=l&7: one coalesced 128B line per warp.
        g_low[(size_t)wtok * RANK + lane] = v[0] * alpha;

        // Publish: every thread fences its writes, then one thread releases.
        __threadfence();
        __syncthreads();
        if (tid == 0) {
            asm volatile("st.release.gpu.global.b32 [%0], %1;"
                         :: "l"(&g_flag[bid]), "r"(1u) : "memory");
        }
        return;
    }

    // ================= CONSUMER =================
    const int idx   = bid - NTILES;
    const int tile  = idx >> 5;          // / NCHUNKS
    const int chunk = idx & (NCHUNKS - 1);
    const int v4    = chunk * TPB + tid;
    const bool valid = (v4 < V4);
    const int vv    = v4 * 4;

    // Independent long-latency work first: B panel (8 rows x 4 cols).
    float4 b[RANK];
#pragma unroll
    for (int r = 0; r < RANK; r++) {
        if (valid)
            b[r] = *reinterpret_cast<const float4*>(B + (size_t)r * VOCAB + vv);
        else
            b[r] = make_float4(0.f, 0.f, 0.f, 0.f);
    }

    // Wait for this tile's producer.
    if (tid == 0) {
        unsigned f;
        do {
            asm volatile("ld.acquire.gpu.global.b32 %0, [%1];"
                         : "=r"(f) : "l"(&g_flag[tile]) : "memory");
            if (!f) __nanosleep(64);
        } while (!f);
    }
    __syncthreads();

    // Load tile's low values into shared (32 tok x 8 r = 64 float4).
    __shared__ float slow[TILE_TOKS * RANK];
    const int tok0 = tile * TILE_TOKS;
    if (tid < TILE_TOKS * RANK / 4) {
        reinterpret_cast<float4*>(slow)[tid] =
            reinterpret_cast<const float4*>(g_low + (size_t)tok0 * RANK)[tid];
    }
    __syncthreads();

    // Handoff bookkeeping: last of the 32 consumers resets for the next replay.
    if (tid == 0) {
        unsigned old = atomicAdd(&g_cnt[tile], 1u);
        if (old == NCHUNKS - 1) {
            g_flag[tile] = 0u;
            g_cnt[tile]  = 0u;
        }
    }

    if (!valid) return;

    float* __restrict__ op = out + (size_t)tok0 * VOCAB + vv;

#pragma unroll 4
    for (int tt = 0; tt < TILE_TOKS; tt++) {
        const float* l = slow + tt * RANK;   // broadcast shared reads
        float4 o;
        o.x = l[0] * b[0].x; o.y = l[0] * b[0].y; o.z = l[0] * b[0].z; o.w = l[0] * b[0].w;
#pragma unroll
        for (int r = 1; r < RANK; r++) {
            o.x = fmaf(l[r], b[r].x, o.x);
            o.y = fmaf(l[r], b[r].y, o.y);
            o.z = fmaf(l[r], b[r].z, o.z);
            o.w = fmaf(l[r], b[r].w, o.w);
        }
        __stcs(reinterpret_cast<float4*>(op), o);   // streaming store
        op += VOCAB;
    }
}

// ---------------------------------------------------------------------------
// Launch: one kernel. Producers occupy the lowest block ids so they are all
// dispatched in wave 1 (no spin deadlock possible).
// ---------------------------------------------------------------------------
extern "C" void kernel_launch(void* const* d_in, const int* in_sizes, int n_in,
                              void* d_out, int out_size)
{
    const float* hidden = (const float*)d_in[0];   // [2,2048,1024]
    const float* A      = (const float*)d_in[1];   // [16,1024,8]
    const float* B      = (const float*)d_in[2];   // [8,32000]
    const float* alpha  = (const float*)d_in[3];   // scalar
    float* out          = (float*)d_out;           // [2,2048,32000]

    const int nblocks = NTILES + NTILES * NCHUNKS; // 128 + 4096 = 4224
    fused_kernel<<<nblocks, TPB>>>(hidden, A, B, alpha, out);
}

// round 10
// speedup vs baseline: 1.0242x; 1.0223x over previous
#include <cuda_runtime.h>
#include <cstdint>

// Problem constants
#define NBUCKETS 16
#define EMBD     1024
#define VOCAB    32000
#define SEQLEN   2048
#define RANK     8
#define BATCH    2
#define NTOK     (BATCH * SEQLEN)          // 4096 tokens
#define BUCKET_SHIFT 7                      // SEQLEN / NBUCKETS = 128 = 1<<7

// Scratch for the low-rank projection (alpha folded in): [NTOK][RANK]
__device__ float g_low[NTOK * RANK];

// ---------------------------------------------------------------------------
// Kernel 1 (v4): low[bt][r] = alpha * sum_e hidden[bt][e] * A[bucket(t)][e][r]
//
// 256 CTAs x 16 tokens (16 | 128: tiles never cross a bucket), 2 CTAs/SM
// (32 KB smem each) -> 4 warps/SMSP to hide LDS/DRAM latency, vs 2 in v3.
// A bucket transposed once into shared; each warp handles 2 tokens so every
// shared A read is amortized. 16-accumulator split-butterfly reduce.
// ---------------------------------------------------------------------------
#define K1_TOKS 16
#define K1_TPB  256
#define TPW     2            // tokens per warp

__global__ __launch_bounds__(K1_TPB, 2)
void lowproj_kernel(const float* __restrict__ hidden,
                    const float* __restrict__ A,
                    const float* __restrict__ alpha_p)
{
    __shared__ float sAT[RANK][EMBD];   // 32 KB, transposed A bucket

    const int tok0   = blockIdx.x * K1_TOKS;
    const int bucket = (tok0 & (SEQLEN - 1)) >> BUCKET_SHIFT;
    const float* __restrict__ Ab = A + (size_t)bucket * EMBD * RANK;

    // Cooperative load + transpose: 2048 float4, 8 per thread.
    for (int i = threadIdx.x; i < EMBD * RANK / 4; i += K1_TPB) {
        float4 v = reinterpret_cast<const float4*>(Ab)[i];
        const int e = i >> 1;
        const int q = (i & 1) * 4;
        sAT[q + 0][e] = v.x;
        sAT[q + 1][e] = v.y;
        sAT[q + 2][e] = v.z;
        sAT[q + 3][e] = v.w;
    }
    __syncthreads();

    const float alpha = alpha_p[0];
    const int wid  = threadIdx.x >> 5;
    const int lane = threadIdx.x & 31;
    const int wtok = tok0 + wid * TPW;           // this warp's 2 tokens
    const float* __restrict__ h0 = hidden + (size_t)wtok * EMBD;

    // acc index i = g*8 + r  (g = token-in-warp 0..1, r = rank)
    float v[TPW * RANK];
#pragma unroll
    for (int i = 0; i < TPW * RANK; i++) v[i] = 0.0f;

    // lane covers e = lane*4 + k*128, k = 0..7
#pragma unroll
    for (int k = 0; k < EMBD / 128; k++) {
        const int e = lane * 4 + k * 128;
        float4 hv[TPW];
#pragma unroll
        for (int g = 0; g < TPW; g++)
            hv[g] = __ldcs(reinterpret_cast<const float4*>(h0 + (size_t)g * EMBD + e));
#pragma unroll
        for (int r = 0; r < RANK; r++) {
            const float4 av = *reinterpret_cast<const float4*>(&sAT[r][e]);
#pragma unroll
            for (int g = 0; g < TPW; g++) {
                v[g * RANK + r] = fmaf(hv[g].x, av.x,
                                  fmaf(hv[g].y, av.y,
                                  fmaf(hv[g].z, av.z,
                                  fmaf(hv[g].w, av.w, v[g * RANK + r]))));
            }
        }
    }

    // Split-butterfly: 16 values over 32 lanes. Four halving stages
    // (m = 16,8,4,2), then a final pairwise butterfly on v[0].
    // Mapping after the stages: lanes l and l^1 both hold the partial for
    // value index (l>>1)&15, i.e. g = l>>4, r = (l>>1)&7.
    int cnt = TPW * RANK;     // 16
#pragma unroll
    for (int m = 16; m >= 2; m >>= 1) {
        const int h = cnt >> 1;
        const bool hi = (lane & m) != 0;
#pragma unroll
        for (int j = 0; j < 8; j++) {
            if (j < h) {
                float mine   = hi ? v[h + j] : v[j];
                float theirs = hi ? v[j]     : v[h + j];
                v[j] = mine + __shfl_xor_sync(0xFFFFFFFFu, theirs, m);
            }
        }
        cnt = h;
    }
    v[0] += __shfl_xor_sync(0xFFFFFFFFu, v[0], 1);

    // Even lanes write 16 consecutive floats (one 64B line per warp).
    if ((lane & 1) == 0)
        g_low[(size_t)wtok * RANK + (lane >> 1)] = v[0] * alpha;
}

// ---------------------------------------------------------------------------
// Kernel 2: out[bt][v] = sum_r low[bt][r] * B[r][v]
// (unchanged — at the streaming-store path ceiling, ~6.1-6.2 TB/s)
// ---------------------------------------------------------------------------
#define T_TILE 64
#define K2_THREADS 256
#define V4 (VOCAB / 4)        // 8000 float4 per row

__global__ __launch_bounds__(K2_THREADS, 4)
void vocabproj_kernel(const float* __restrict__ B,
                      float* __restrict__ out)
{
    const int v4  = blockIdx.x * K2_THREADS + threadIdx.x;  // float4 column index
    const bool valid = (v4 < V4);
    const int v = v4 * 4;

    // Load B panel into registers: 8 rows x 4 cols
    float4 b[RANK];
#pragma unroll
    for (int r = 0; r < RANK; r++) {
        if (valid)
            b[r] = *reinterpret_cast<const float4*>(B + (size_t)r * VOCAB + v);
        else
            b[r] = make_float4(0.f, 0.f, 0.f, 0.f);
    }

    // Cooperative load of this block's token-tile of low into shared
    __shared__ float slow[T_TILE * RANK];    // 2 KB
    const int tok0 = blockIdx.y * T_TILE;
    for (int i = threadIdx.x; i < T_TILE * RANK / 4; i += K2_THREADS) {
        reinterpret_cast<float4*>(slow)[i] =
            reinterpret_cast<const float4*>(g_low + (size_t)tok0 * RANK)[i];
    }
    __syncthreads();

    if (!valid) return;

    float* __restrict__ op = out + (size_t)tok0 * VOCAB + v;

#pragma unroll 4
    for (int tt = 0; tt < T_TILE; tt++) {
        const float* l = slow + tt * RANK;   // broadcast shared reads
        float4 o;
        o.x = l[0] * b[0].x; o.y = l[0] * b[0].y; o.z = l[0] * b[0].z; o.w = l[0] * b[0].w;
#pragma unroll
        for (int r = 1; r < RANK; r++) {
            o.x = fmaf(l[r], b[r].x, o.x);
            o.y = fmaf(l[r], b[r].y, o.y);
            o.z = fmaf(l[r], b[r].z, o.z);
            o.w = fmaf(l[r], b[r].w, o.w);
        }
        __stcs(reinterpret_cast<float4*>(op), o);   // streaming store
        op += VOCAB;
    }
}

// ---------------------------------------------------------------------------
// Launch
// ---------------------------------------------------------------------------
extern "C" void kernel_launch(void* const* d_in, const int* in_sizes, int n_in,
                              void* d_out, int out_size)
{
    const float* hidden = (const float*)d_in[0];   // [2,2048,1024]
    const float* A      = (const float*)d_in[1];   // [16,1024,8]
    const float* B      = (const float*)d_in[2];   // [8,32000]
    const float* alpha  = (const float*)d_in[3];   // scalar
    float* out          = (float*)d_out;           // [2,2048,32000]

    lowproj_kernel<<<NTOK / K1_TOKS, K1_TPB>>>(hidden, A, alpha);

    dim3 grid2((V4 + K2_THREADS - 1) / K2_THREADS,   // 32
               NTOK / T_TILE);                       // 64
    vocabproj_kernel<<<grid2, K2_THREADS>>>(B, out);
}